// round 2
// baseline (speedup 1.0000x reference)
#include <cuda_runtime.h>
#include <cuda_bf16.h>
#include <math.h>
#include <limits.h>

#define BATCH 4096
#define DIM   512
#define NCLS  128

// Scratch (allocation-free: __device__ globals)
__device__ int    g_cls_cnt[NCLS];
__device__ int    g_cls_memb[NCLS * BATCH];  // 2 MB
__device__ double g_sum;
__device__ int    g_count;

__global__ void k_zero() {
    int t = threadIdx.x;
    if (t < NCLS) g_cls_cnt[t] = 0;
    if (t == 0) { g_sum = 0.0; g_count = 0; }
}

// labels are int32 (JAX x64 disabled: jnp.int64 materializes as int32)
__global__ void k_build(const int* __restrict__ labels) {
    int i = blockIdx.x * blockDim.x + threadIdx.x;
    if (i < BATCH) {
        int c = labels[i];
        if (c < 0) c = 0;
        if (c >= NCLS) c = NCLS - 1;
        int pos = atomicAdd(&g_cls_cnt[c], 1);
        g_cls_memb[c * BATCH + pos] = i;
    }
}

// One block per anchor row i. 128 threads = 4 warps.
__global__ void __launch_bounds__(128) k_main(const float* __restrict__ batch,
                                              const int* __restrict__ labels,
                                              const int* __restrict__ anchors,
                                              const int* __restrict__ negatives) {
    const int i = blockIdx.x;
    int c = labels[i];
    if (c < 0) c = 0;
    if (c >= NCLS) c = NCLS - 1;
    const int cnt = g_cls_cnt[c];
    // posmask row count = cnt-1; valid iff cnt-1 > 1  =>  cnt >= 3
    if (cnt < 3) return;

    __shared__ float sh_a[DIM];
    __shared__ float sh_sq_part[4];
    __shared__ float sh_sqi;
    __shared__ float sh_wbest[4];
    __shared__ int   sh_widx[4];
    __shared__ int   sh_pidx;
    __shared__ float sh_dap, sh_dan;

    const int tid  = threadIdx.x;
    const int lane = tid & 31;
    const int wid  = tid >> 5;

    // Load anchor row into smem, compute sq_i
    float sqp = 0.f;
    #pragma unroll
    for (int k = 0; k < DIM / 128; k++) {
        int e = tid + 128 * k;
        float v = batch[(size_t)i * DIM + e];
        sh_a[e] = v;
        sqp = fmaf(v, v, sqp);
    }
    #pragma unroll
    for (int o = 16; o; o >>= 1) sqp += __shfl_xor_sync(0xFFFFFFFFu, sqp, o);
    if (lane == 0) sh_sq_part[wid] = sqp;
    __syncthreads();
    if (tid == 0) sh_sqi = sh_sq_part[0] + sh_sq_part[1] + sh_sq_part[2] + sh_sq_part[3];
    __syncthreads();
    const float sqi = sh_sqi;

    // Hardest-positive argmin over same-class members (excluding self).
    // d2 = sq_i + sq_j - 2*dot  (same formula as reference's matrix; sqrt monotone)
    const int* memb = &g_cls_memb[c * BATCH];
    float bestd = INFINITY;
    int   bestj = INT_MAX;
    for (int m = wid; m < cnt; m += 4) {
        int j = memb[m];
        if (j == i) continue;
        const float* brow = batch + (size_t)j * DIM;
        float dot = 0.f, sqb = 0.f;
        #pragma unroll
        for (int k = 0; k < DIM / 32; k++) {
            float bv = brow[lane + 32 * k];
            dot = fmaf(sh_a[lane + 32 * k], bv, dot);
            sqb = fmaf(bv, bv, sqb);
        }
        #pragma unroll
        for (int o = 16; o; o >>= 1) {
            dot += __shfl_xor_sync(0xFFFFFFFFu, dot, o);
            sqb += __shfl_xor_sync(0xFFFFFFFFu, sqb, o);
        }
        float d2 = sqi + sqb - 2.f * dot;
        if (d2 < bestd || (d2 == bestd && j < bestj)) { bestd = d2; bestj = j; }
    }
    if (lane == 0) { sh_wbest[wid] = bestd; sh_widx[wid] = bestj; }
    __syncthreads();
    if (tid == 0) {
        float bd = INFINITY; int bj = INT_MAX;
        #pragma unroll
        for (int w = 0; w < 4; w++) {
            if (sh_wbest[w] < bd || (sh_wbest[w] == bd && sh_widx[w] < bj)) {
                bd = sh_wbest[w]; bj = sh_widx[w];
            }
        }
        sh_pidx = bj;
    }
    __syncthreads();

    const int p = sh_pidx;
    const int aidx = anchors[i];
    const int nidx = negatives[i];

    // d_ap / d_an via direct squared-diff sums (matches reference _pair_dist)
    if (wid == 0) {
        const float* xr = batch + (size_t)aidx * DIM;
        const float* yr = batch + (size_t)p * DIM;
        float s = 0.f;
        #pragma unroll
        for (int k = 0; k < DIM / 32; k++) {
            float d = xr[lane + 32 * k] - yr[lane + 32 * k];
            s = fmaf(d, d, s);
        }
        #pragma unroll
        for (int o = 16; o; o >>= 1) s += __shfl_xor_sync(0xFFFFFFFFu, s, o);
        if (lane == 0) sh_dap = sqrtf(fmaxf(s, 1e-12f));
    }
    if (wid == 1) {
        const float* xr = batch + (size_t)aidx * DIM;
        const float* yr = batch + (size_t)nidx * DIM;
        float s = 0.f;
        #pragma unroll
        for (int k = 0; k < DIM / 32; k++) {
            float d = xr[lane + 32 * k] - yr[lane + 32 * k];
            s = fmaf(d, d, s);
        }
        #pragma unroll
        for (int o = 16; o; o >>= 1) s += __shfl_xor_sync(0xFFFFFFFFu, s, o);
        if (lane == 0) sh_dan = sqrtf(fmaxf(s, 1e-12f));
    }
    __syncthreads();

    if (tid == 0) {
        // (s_an - s_ap)/TEMP = (d_ap - d_an)/(2*0.05) = (d_ap - d_an)*10
        float x = (sh_dap - sh_dan) * 10.f;
        float per = fmaxf(x, 0.f) + log1pf(expf(-fabsf(x)));
        atomicAdd(&g_sum, (double)per);
        atomicAdd(&g_count, 1);
    }
}

__global__ void k_final(float* __restrict__ out) {
    out[0] = (float)(g_sum / (double)g_count);
}

extern "C" void kernel_launch(void* const* d_in, const int* in_sizes, int n_in,
                              void* d_out, int out_size) {
    const float* batch     = (const float*)d_in[0];
    const int*   labels    = (const int*)d_in[1];
    const int*   anchors   = (const int*)d_in[2];
    const int*   negatives = (const int*)d_in[3];
    float* out = (float*)d_out;

    k_zero<<<1, 256>>>();
    k_build<<<(BATCH + 255) / 256, 256>>>(labels);
    k_main<<<BATCH, 128>>>(batch, labels, anchors, negatives);
    k_final<<<1, 1>>>(out);
}

// round 6
// speedup vs baseline: 1.0429x; 1.0429x over previous
#include <cuda_runtime.h>
#include <math.h>
#include <limits.h>

#define BATCH 4096
#define DIM   512
#define NCLS  128
#define BPC   2                  // blocks per class
#define NBLK  (NCLS * BPC)
#define CH    16                 // smem chunk rows
#define MAXM  1024               // member list cap (real data: ~32 per class)

// Per-block partials, written unconditionally every replay -> no zeroing kernel.
__device__ double g_partial[NBLK];
__device__ int    g_pcount[NBLK];

__global__ void __launch_bounds__(256, 2) k_class(
    const float* __restrict__ batch,
    const int*   __restrict__ labels,
    const int*   __restrict__ anchors,
    const int*   __restrict__ negatives)
{
    const int c    = blockIdx.x >> 1;
    const int half = blockIdx.x & 1;
    const int tid  = threadIdx.x;
    const int lane = tid & 31;
    const int wid  = tid >> 5;          // 0..7
    const int slot = half * 8 + wid;    // 0..15 anchor slot across the class's 2 blocks

    __shared__ __align__(16) float  sh_rows[CH][DIM];
    __shared__ int    sh_raw[MAXM];
    __shared__ int    sh_memb[MAXM];    // sorted (deterministic across the class's 2 blocks)
    __shared__ double sh_wsum[8];
    __shared__ int    sh_wcnt[8];
    __shared__ int    sh_cnt;

    // ---- build member list (atomic order is nondeterministic) ----
    if (tid == 0) sh_cnt = 0;
    __syncthreads();
    for (int s = tid; s < BATCH; s += 256) {
        if (labels[s] == c) {
            int pos = atomicAdd(&sh_cnt, 1);
            if (pos < MAXM) sh_raw[pos] = s;
        }
    }
    __syncthreads();
    const int cnt = min(sh_cnt, MAXM);

    // ---- rank-sort ascending: identical list in both blocks of this class ----
    for (int t = tid; t < cnt; t += 256) {
        int v = sh_raw[t];
        int rank = 0;
        for (int k = 0; k < cnt; ++k) rank += (sh_raw[k] < v);
        sh_memb[rank] = v;
    }
    __syncthreads();

    double wsum = 0.0;
    int    wcnt = 0;

    if (cnt >= 3) {   // valid iff (cnt-1) > 1
        const int nrounds = (cnt + 15) >> 4;        // anchors per slot
        const int npass   = (nrounds + 3) >> 2;     // 4 anchors resident per warp per pass
        const int nchunk  = (cnt + CH - 1) / CH;

        for (int pass = 0; pass < npass; ++pass) {
            int   am[4]; bool av[4];
            float areg[4][16];
            float bestd[4]; int bestj[4];
            #pragma unroll
            for (int r = 0; r < 4; ++r) {
                int rr = 4 * pass + r;
                int m  = slot + 16 * rr;
                av[r] = (rr < nrounds) && (m < cnt);
                am[r] = av[r] ? sh_memb[m] : 0;
                bestd[r] = INFINITY; bestj[r] = INT_MAX;
                if (av[r]) {
                    const float* ap = batch + (size_t)am[r] * DIM;
                    #pragma unroll
                    for (int k = 0; k < 16; ++k) areg[r][k] = ap[lane + 32 * k];
                }
            }

            for (int chb = 0; chb < nchunk; ++chb) {
                const int base = chb * CH;
                const int nrow = min(CH, cnt - base);
                __syncthreads();
                {   // cooperative chunk load: 16 threads per row, float4
                    int row = tid >> 4, sub = tid & 15;
                    if (row < nrow) {
                        const float4* src = (const float4*)(batch + (size_t)sh_memb[base + row] * DIM);
                        float4*       dst = (float4*)&sh_rows[row][0];
                        #pragma unroll
                        for (int k = 0; k < 8; ++k) dst[sub + 16 * k] = src[sub + 16 * k];
                    }
                }
                __syncthreads();

                for (int q = 0; q < nrow; ++q) {
                    float b[16];
                    #pragma unroll
                    for (int k = 0; k < 16; ++k) b[k] = sh_rows[q][lane + 32 * k];
                    const int j = sh_memb[base + q];
                    #pragma unroll
                    for (int r = 0; r < 4; ++r) {
                        if (!av[r] || j == am[r]) continue;
                        float acc = 0.f;
                        #pragma unroll
                        for (int k = 0; k < 16; ++k) { float d = areg[r][k] - b[k]; acc = fmaf(d, d, acc); }
                        #pragma unroll
                        for (int o = 16; o; o >>= 1) acc += __shfl_xor_sync(0xFFFFFFFFu, acc, o);
                        if (acc < bestd[r] || (acc == bestd[r] && j < bestj[r])) { bestd[r] = acc; bestj[r] = j; }
                    }
                }
            }

            // ---- epilogue for this pass's anchors ----
            #pragma unroll
            for (int r = 0; r < 4; ++r) {
                if (!av[r]) continue;
                const int t    = am[r];
                const int a    = anchors[t];
                const int nidx = negatives[t];
                const int p    = bestj[r];
                float d_ap, d_an;
                if (a == t) {   // anchor row == mining row: reuse bestd and areg
                    d_ap = sqrtf(fmaxf(bestd[r], 1e-12f));
                    const float* nr_ = batch + (size_t)nidx * DIM;
                    float acc = 0.f;
                    #pragma unroll
                    for (int k = 0; k < 16; ++k) { float d = areg[r][k] - nr_[lane + 32 * k]; acc = fmaf(d, d, acc); }
                    #pragma unroll
                    for (int o = 16; o; o >>= 1) acc += __shfl_xor_sync(0xFFFFFFFFu, acc, o);
                    d_an = sqrtf(fmaxf(acc, 1e-12f));
                } else {        // general path (not hit with arange anchors, kept for correctness)
                    const float* ar_ = batch + (size_t)a * DIM;
                    const float* pr_ = batch + (size_t)p * DIM;
                    const float* nr_ = batch + (size_t)nidx * DIM;
                    float acc1 = 0.f, acc2 = 0.f;
                    #pragma unroll
                    for (int k = 0; k < 16; ++k) {
                        float va = ar_[lane + 32 * k];
                        float d1 = va - pr_[lane + 32 * k];
                        float d2 = va - nr_[lane + 32 * k];
                        acc1 = fmaf(d1, d1, acc1); acc2 = fmaf(d2, d2, acc2);
                    }
                    #pragma unroll
                    for (int o = 16; o; o >>= 1) {
                        acc1 += __shfl_xor_sync(0xFFFFFFFFu, acc1, o);
                        acc2 += __shfl_xor_sync(0xFFFFFFFFu, acc2, o);
                    }
                    d_ap = sqrtf(fmaxf(acc1, 1e-12f));
                    d_an = sqrtf(fmaxf(acc2, 1e-12f));
                }
                if (lane == 0) {
                    // (s_an - s_ap)/TEMP = (d_ap - d_an)/(2*0.05)
                    float x   = (d_ap - d_an) * 10.f;
                    float per = fmaxf(x, 0.f) + log1pf(expf(-fabsf(x)));
                    wsum += (double)per; wcnt += 1;
                }
            }
        }
    }

    if (lane == 0) { sh_wsum[wid] = wsum; sh_wcnt[wid] = wcnt; }
    __syncthreads();
    if (tid == 0) {
        double s = 0.0; int n = 0;
        #pragma unroll
        for (int w = 0; w < 8; ++w) { s += sh_wsum[w]; n += sh_wcnt[w]; }
        g_partial[blockIdx.x] = s;
        g_pcount[blockIdx.x]  = n;
    }
}

__global__ void k_final(float* __restrict__ out) {
    __shared__ __align__(16) double ssum[NBLK];
    __shared__ int    scnt[NBLK];
    int t = threadIdx.x;
    ssum[t] = g_partial[t];
    scnt[t] = g_pcount[t];
    __syncthreads();
    for (int o = NBLK / 2; o; o >>= 1) {
        if (t < o) { ssum[t] += ssum[t + o]; scnt[t] += scnt[t + o]; }
        __syncthreads();
    }
    if (t == 0) out[0] = (float)(ssum[0] / (double)scnt[0]);
}

extern "C" void kernel_launch(void* const* d_in, const int* in_sizes, int n_in,
                              void* d_out, int out_size) {
    const float* batch     = (const float*)d_in[0];
    const int*   labels    = (const int*)d_in[1];
    const int*   anchors   = (const int*)d_in[2];
    const int*   negatives = (const int*)d_in[3];
    float* out = (float*)d_out;

    k_class<<<NBLK, 256>>>(batch, labels, anchors, negatives);
    k_final<<<1, NBLK>>>(out);
}